// round 15
// baseline (speedup 1.0000x reference)
#include <cuda_runtime.h>
#include <cuda_fp16.h>
#include <math.h>
#include <stdint.h>

#define BATCH   8
#define SEQLEN  4096
#define DIM     512
#define MROWS   (BATCH * SEQLEN)   // 32768
#define CHUNK_S 64
#define NCHUNK_S (SEQLEN / CHUNK_S)  // 64

// ================= static scratch =================
// packed coefficients: lo = 1-a (fp16), hi = b (fp16)
__device__ __align__(16) __half2 g_ab[(size_t)MROWS * DIM];   // 64 MB
__device__ float g_P  [BATCH * NCHUNK_S * DIM];
__device__ float g_Q  [BATCH * NCHUNK_S * DIM];
__device__ float g_Hin[BATCH * NCHUNK_S * DIM];               // 8 MB

// fp16 operands. A3 = [hs | x] : 32768 x 1024
__device__ __align__(16) __half g_A3[(size_t)MROWS * 1024];
__device__ __align__(16) __half g_W1[1024 * 512];    // interleaved [Wg;B]
__device__ __align__(16) __half g_W3[512 * 1024];    // [C | D]

// ================= PTX helpers (sm_80+ family-safe) ========
__device__ __forceinline__ uint32_t smem_u32(const void* p) {
    uint32_t a;
    asm("{ .reg .u64 t; cvta.to.shared.u64 t, %1; cvt.u32.u64 %0, t; }"
        : "=r"(a) : "l"(p));
    return a;
}
__device__ __forceinline__ void cp16(uint32_t s, const void* g) {
    asm volatile("cp.async.cg.shared.global [%0], [%1], 16;"
                 :: "r"(s), "l"(__cvta_generic_to_global(g)) : "memory");
}
#define CP_COMMIT() asm volatile("cp.async.commit_group;" ::: "memory")
#define CP_WAIT(n)  asm volatile("cp.async.wait_group %0;" :: "n"(n) : "memory")

#define LDSM4(r0, r1, r2, r3, addr) \
    asm volatile("ldmatrix.sync.aligned.m8n8.x4.shared.b16 {%0,%1,%2,%3}, [%4];" \
                 : "=r"(r0), "=r"(r1), "=r"(r2), "=r"(r3) : "r"(addr))

#define MMAH(c, a, b0, b1) \
    asm volatile("mma.sync.aligned.m16n8k16.row.col.f32.f16.f16.f32 " \
                 "{%0,%1,%2,%3}, {%4,%5,%6,%7}, {%8,%9}, {%0,%1,%2,%3};" \
                 : "+f"((c)[0]), "+f"((c)[1]), "+f"((c)[2]), "+f"((c)[3]) \
                 : "r"((a)[0]), "r"((a)[1]), "r"((a)[2]), "r"((a)[3]), \
                   "r"(b0), "r"(b1))

// smem tile: 128 rows x 64 fp16 (128B data), row stride 144B.
// 144*r mod 128 over r=0..7 -> all eight 16B banks: ldmatrix conflict-free.
#define T_STRIDE 144
#define T_BYTES  (128 * T_STRIDE)          // 18432
#define BUF_BYTES (2 * T_BYTES)            // A + W = 36864
#define SMEM_REQ  (2 * BUF_BYTES)          // 73728 (double buffer; 3 CTAs/SM)

// =======================================================================
// merged conv kernel: W1, W3, and x->A3 in one launch
//   idx <  524288          : W1 element
//   idx < 1048576          : W3 element
//   else                   : one float4 of x (j = idx - 1048576)
// =======================================================================
__global__ void conv_all_kernel(const float* __restrict__ Wg, const float* __restrict__ B,
                                const float* __restrict__ C,  const float* __restrict__ D,
                                const float* __restrict__ x)
{
    size_t idx = (size_t)blockIdx.x * blockDim.x + threadIdx.x;
    if (idx < 1024 * 512) {
        int r = (int)(idx >> 9), k = (int)(idx & 511), h = r >> 1;
        float v = (r & 1) ? B[h * 512 + k] : Wg[h * 512 + k];
        g_W1[idx] = __float2half_rn(v);
    } else if (idx < 2 * 1024 * 512) {
        int j = (int)(idx - 1024 * 512);
        int n = j >> 10, k = j & 1023;
        float v = (k < 512) ? C[n * 512 + k] : D[n * 512 + k - 512];
        g_W3[j] = __float2half_rn(v);
    } else {
        size_t j = idx - 2 * 1024 * 512;        // float4 index over x
        int cv = (int)(j & 127);
        int m  = (int)(j >> 7);
        float4 v = *(const float4*)&x[(size_t)m * 512 + cv * 4];
        size_t o = (size_t)m * 1024 + 512 + cv * 4;
        *(__half2*)&g_A3[o]     = __floats2half2_rn(v.x, v.y);
        *(__half2*)&g_A3[o + 2] = __floats2half2_rn(v.z, v.w);
    }
}

// =======================================================================
// HMMA mainloop: CTA 128x128, 4 warps, warp tile 64x64, K-chunk 64,
// 2-stage cp.async, single-fp16 operands
// =======================================================================
__device__ __forceinline__ void issue_chunk(
    uint32_t tb, int tid, int k0,
    const __half* __restrict__ A, int lda,
    const __half* __restrict__ W, int ldw)
{
    #pragma unroll
    for (int i = 0; i < 8; ++i) {
        int v = i * 128 + tid;              // 0..1023
        int r = v >> 3, ch = v & 7;         // row 0..127, 16B-chunk 0..7
        uint32_t so = (uint32_t)(r * T_STRIDE + ch * 16);
        int go = k0 + ch * 8;
        cp16(tb +           so, A + (size_t)r * lda + go);
        cp16(tb + T_BYTES + so, W + (size_t)r * ldw + go);
    }
    CP_COMMIT();
}

template<int NC>
__device__ __forceinline__ void hmma_mainloop(
    uint32_t sb,
    const __half* __restrict__ A, int lda,
    const __half* __restrict__ W, int ldw,
    float acc[4][8][4])
{
    const int tid  = threadIdx.x;
    const int wid  = tid >> 5, lane = tid & 31;
    const int wm   = (wid >> 1) * 64;
    const int wn   = (wid & 1) * 64;
    const uint32_t aSel = (uint32_t)((lane & 15) * T_STRIDE + (lane >> 4) * 16);
    const uint32_t bSel = (uint32_t)((((lane >> 4) << 3) + (lane & 7)) * T_STRIDE
                                     + ((lane >> 3) & 1) * 16);

    issue_chunk(sb,             tid, 0,  A, lda, W, ldw);
    issue_chunk(sb + BUF_BYTES, tid, 64, A, lda, W, ldw);

    #pragma unroll 1
    for (int c = 0; c < NC; ++c) {
        if (c + 1 == NC) { CP_WAIT(0); } else { CP_WAIT(1); }
        __syncthreads();

        const uint32_t tb = sb + (uint32_t)(c & 1) * BUF_BYTES;
        const uint32_t At = tb + (uint32_t)wm * T_STRIDE + aSel;
        const uint32_t Wt = tb + T_BYTES + (uint32_t)wn * T_STRIDE + bSel;

        #pragma unroll
        for (int kk = 0; kk < 4; ++kk) {
            const uint32_t ko = kk * 32;    // 16 fp16 = 32B per k16 step
            uint32_t ah[4][4];
            #pragma unroll
            for (int mb = 0; mb < 4; ++mb)
                LDSM4(ah[mb][0], ah[mb][1], ah[mb][2], ah[mb][3],
                      At + mb * (16 * T_STRIDE) + ko);
            #pragma unroll
            for (int nb = 0; nb < 4; ++nb) {
                uint32_t wh[4];
                LDSM4(wh[0], wh[1], wh[2], wh[3], Wt + nb * (16 * T_STRIDE) + ko);
                #pragma unroll
                for (int mb = 0; mb < 4; ++mb) {
                    MMAH(acc[mb][2 * nb],     ah[mb], wh[0], wh[1]);
                    MMAH(acc[mb][2 * nb + 1], ah[mb], wh[2], wh[3]);
                }
            }
        }
        __syncthreads();
        if (c + 2 < NC)
            issue_chunk(sb + (uint32_t)(c & 1) * BUF_BYTES, tid, (c + 2) * 64,
                        A, lda, W, ldw);
    }
}

// =======================================================================
// Stage 1: raw = x @ W1^T (M=32768, N=1024, K=512) -> (1-a, b) fp16 + P,Q
// grid (8, 256), 128 threads
// =======================================================================
__global__ __launch_bounds__(128, 3)
void hmma_stage1_kernel(const float* __restrict__ Avec,
                        const float* __restrict__ bias_h)
{
    extern __shared__ __align__(16) char smem[];
    const uint32_t sb = smem_u32(smem);

    float acc[4][8][4];
    #pragma unroll
    for (int i = 0; i < 4; ++i)
        #pragma unroll
        for (int j = 0; j < 8; ++j)
            #pragma unroll
            for (int q = 0; q < 4; ++q) acc[i][j][q] = 0.f;

    const int row0 = blockIdx.y * 128;
    const int col0 = blockIdx.x * 128;

    hmma_mainloop<8>(sb,
                     g_A3 + 512 + (size_t)row0 * 1024, 1024,
                     g_W1 + (size_t)col0 * 512, 512,
                     acc);

    // -------- epilogue: gate math, quantize (1-a, b) to fp16, restage ------
    const int tid = threadIdx.x, wid = tid >> 5, lane = tid & 31;
    const int wm = (wid >> 1) * 64, wn = (wid & 1) * 64;
    const int g = lane >> 2, tig = lane & 3;
    const int hbase = col0 >> 1;

    float* sA = (float*)smem;              // [128][65]  quantized (1-a)
    float* sB = sA + 128 * 65;             // [128][65]  quantized b

    #pragma unroll
    for (int mb = 0; mb < 4; ++mb) {
        #pragma unroll
        for (int j = 0; j < 8; ++j) {
            int h_loc = (wn + (j >> 1) * 16 + (j & 1) * 8 + 2 * tig) >> 1;
            int hg = hbase + h_loc;
            float Ah = Avec[hg], Bh = bias_h[hg];
            int m0 = wm + mb * 16 + g;

            float g0 = 1.0f / (1.0f + __expf(-acc[mb][j][0]));
            g0 = fminf(fmaxf(g0, 0.05f), 0.95f);
            sA[m0 * 65 + h_loc] = __half2float(__float2half_rn(g0 * (1.0f - Ah)));
            sB[m0 * 65 + h_loc] = __half2float(__float2half_rn(g0 * (acc[mb][j][1] + Bh)));

            float g1 = 1.0f / (1.0f + __expf(-acc[mb][j][2]));
            g1 = fminf(fmaxf(g1, 0.05f), 0.95f);
            sA[(m0 + 8) * 65 + h_loc] = __half2float(__float2half_rn(g1 * (1.0f - Ah)));
            sB[(m0 + 8) * 65 + h_loc] = __half2float(__float2half_rn(g1 * (acc[mb][j][3] + Bh)));
        }
    }
    __syncthreads();

    // coalesced packed write (values already half-representable -> exact)
    const int hh = tid & 63, rg = tid >> 6;
    #pragma unroll
    for (int r = 0; r < 64; ++r) {
        int row = rg * 64 + r;
        size_t gb = (size_t)(row0 + row) * DIM + hbase + hh;
        g_ab[gb] = __floats2half2_rn(sA[row * 65 + hh], sB[row * 65 + hh]);
    }

    // sub-chunk summaries (64 rows): P = prod(a), Q = local final (h_in=0),
    // computed from the QUANTIZED coefficients for exact carry consistency.
    {
        const int sc = tid >> 6;           // 0..1
        const int hl = tid & 63;
        float p = 1.0f, q = 0.0f;
        #pragma unroll 4
        for (int r = sc * 64; r < sc * 64 + 64; ++r) {
            float a  = 1.0f - sA[r * 65 + hl];
            float bb = sB[r * 65 + hl];
            q = fmaf(a, q, bb);
            p *= a;
        }
        size_t o = ((size_t)blockIdx.y * 2 + sc) * DIM + hbase + hl;
        g_P[o] = p;
        g_Q[o] = q;
    }
}

// =======================================================================
// carry: Hillis-Steele log-depth scan of affine maps over the 64 chunks.
// grid 512 (b = blk>>6, h-group = blk&63 covering 8 h), block 512
// (c = tid>>3, hl = tid&7). Exclusive prefix -> g_Hin.
// =======================================================================
__global__ __launch_bounds__(512) void scan_carry_kernel()
{
    __shared__ float sP[64][8];
    __shared__ float sQ[64][8];
    const int b  = blockIdx.x >> 6;
    const int hg = blockIdx.x & 63;
    const int tid = threadIdx.x;
    const int c  = tid >> 3, hl = tid & 7;
    const int h  = hg * 8 + hl;
    const size_t o = ((size_t)b * NCHUNK_S + c) * DIM + h;

    float p = g_P[o], q = g_Q[o];
    sP[c][hl] = p; sQ[c][hl] = q;
    __syncthreads();

    #pragma unroll
    for (int d = 1; d < 64; d <<= 1) {
        float pp = 1.0f, pq = 0.0f;
        if (c >= d) { pp = sP[c - d][hl]; pq = sQ[c - d][hl]; }
        __syncthreads();
        if (c >= d) { q = fmaf(p, pq, q); p *= pp; }
        sP[c][hl] = p; sQ[c][hl] = q;
        __syncthreads();
    }

    // exclusive prefix: Hin[c] = (c==0) ? 0 : inclusive[c-1].Q
    g_Hin[o] = (c == 0) ? 0.0f : sQ[c - 1][hl];
}

// =======================================================================
// final scan: 128 threads x 4 adjacent h each; 16B coefficient loads,
// 8B fp16 stores. grid 512.
// =======================================================================
__global__ __launch_bounds__(128) void scan_final_kernel()
{
    const int bc = blockIdx.x;            // b*64 + cs
    const int b  = bc >> 6;
    const int cs = bc & 63;
    const int h0 = threadIdx.x * 4;       // 4 adjacent h

    float4 hin = *(const float4*)&g_Hin[(size_t)bc * DIM + h0];
    float hc0 = hin.x, hc1 = hin.y, hc2 = hin.z, hc3 = hin.w;

    const size_t base = ((size_t)b * SEQLEN + (size_t)cs * CHUNK_S) * DIM + h0;
    #pragma unroll 4
    for (int t = 0; t < CHUNK_S; ++t) {
        float4 r = *reinterpret_cast<const float4*>(&g_ab[base + (size_t)t * DIM]);
        __half2 ab0 = *reinterpret_cast<__half2*>(&r.x);
        __half2 ab1 = *reinterpret_cast<__half2*>(&r.y);
        __half2 ab2 = *reinterpret_cast<__half2*>(&r.z);
        __half2 ab3 = *reinterpret_cast<__half2*>(&r.w);
        hc0 = fmaf(1.0f - __half2float(__low2half(ab0)), hc0, __half2float(__high2half(ab0)));
        hc1 = fmaf(1.0f - __half2float(__low2half(ab1)), hc1, __half2float(__high2half(ab1)));
        hc2 = fmaf(1.0f - __half2float(__low2half(ab2)), hc2, __half2float(__high2half(ab2)));
        hc3 = fmaf(1.0f - __half2float(__low2half(ab3)), hc3, __half2float(__high2half(ab3)));
        const size_t m = (size_t)(b * SEQLEN + cs * CHUNK_S + t);
        __half2 o0 = __floats2half2_rn(hc0, hc1);
        __half2 o1 = __floats2half2_rn(hc2, hc3);
        float2 ov;
        ov.x = *reinterpret_cast<float*>(&o0);
        ov.y = *reinterpret_cast<float*>(&o1);
        *(float2*)&g_A3[m * 1024 + h0] = ov;
    }
}

// =======================================================================
// Stage 3: y = (hs@C^T + x@D^T + bias_y)*scale, K=1024, single-fp16 W
// grid (4, 256), 128 threads
// =======================================================================
__global__ __launch_bounds__(128, 3)
void hmma_stage3_kernel(const float* __restrict__ bias_y, float* __restrict__ out)
{
    extern __shared__ __align__(16) char smem[];
    const uint32_t sb = smem_u32(smem);

    float acc[4][8][4];
    #pragma unroll
    for (int i = 0; i < 4; ++i)
        #pragma unroll
        for (int j = 0; j < 8; ++j)
            #pragma unroll
            for (int q = 0; q < 4; ++q) acc[i][j][q] = 0.f;

    const int row0 = blockIdx.y * 128;
    const int col0 = blockIdx.x * 128;

    hmma_mainloop<16>(sb,
                      g_A3 + (size_t)row0 * 1024, 1024,
                      g_W3 + (size_t)col0 * 1024, 1024,
                      acc);

    const int tid = threadIdx.x, wid = tid >> 5, lane = tid & 31;
    const int wm = (wid >> 1) * 64, wn = (wid & 1) * 64;
    const int g = lane >> 2, tig = lane & 3;
    const float scale = 0.04419417382415922f;   // 1/sqrt(512)

    float* sY = (float*)smem;                   // [128][132]

    #pragma unroll
    for (int mb = 0; mb < 4; ++mb) {
        #pragma unroll
        for (int j = 0; j < 8; ++j) {
            int n0 = wn + (j >> 1) * 16 + (j & 1) * 8 + 2 * tig;
            float by0 = bias_y[col0 + n0], by1 = bias_y[col0 + n0 + 1];
            int m0 = wm + mb * 16 + g;
            sY[m0 * 132 + n0]           = (acc[mb][j][0] + by0) * scale;
            sY[m0 * 132 + n0 + 1]       = (acc[mb][j][1] + by1) * scale;
            sY[(m0 + 8) * 132 + n0]     = (acc[mb][j][2] + by0) * scale;
            sY[(m0 + 8) * 132 + n0 + 1] = (acc[mb][j][3] + by1) * scale;
        }
    }
    __syncthreads();

    // vectorized store: 4096 float4 over 128 threads = 32 iterations
    #pragma unroll 8
    for (int i = 0; i < 32; ++i) {
        int v   = i * 128 + tid;
        int row = v >> 5;
        int c4  = v & 31;
        float4 val = *(const float4*)&sY[row * 132 + c4 * 4];
        *(float4*)&out[(size_t)(row0 + row) * DIM + col0 + c4 * 4] = val;
    }
}

// =======================================================================
extern "C" void kernel_launch(void* const* d_in, const int* in_sizes, int n_in,
                              void* d_out, int out_size)
{
    const float* x      = (const float*)d_in[0];
    const float* Avec   = (const float*)d_in[1];
    const float* B      = (const float*)d_in[2];
    const float* C      = (const float*)d_in[3];
    const float* Dm     = (const float*)d_in[4];
    const float* Wg     = (const float*)d_in[5];
    const float* bias_h = (const float*)d_in[6];
    const float* bias_y = (const float*)d_in[7];
    float* out = (float*)d_out;

    cudaFuncSetAttribute(hmma_stage1_kernel,
                         cudaFuncAttributeMaxDynamicSharedMemorySize, SMEM_REQ);
    cudaFuncSetAttribute(hmma_stage3_kernel,
                         cudaFuncAttributeMaxDynamicSharedMemorySize, SMEM_REQ);

    // merged conversions: W1 + W3 + x->A3
    const int conv_items = 2 * 1024 * 512 + MROWS * (DIM / 4);
    conv_all_kernel<<<conv_items / 256, 256>>>(Wg, B, C, Dm, x);

    hmma_stage1_kernel<<<dim3(8, MROWS / 128), 128, SMEM_REQ>>>(Avec, bias_h);

    scan_carry_kernel<<<BATCH * 64, 512>>>();
    scan_final_kernel<<<BATCH * NCHUNK_S, 128>>>();

    hmma_stage3_kernel<<<dim3(4, MROWS / 128), 128, SMEM_REQ>>>(bias_y, out);
}

// round 16
// speedup vs baseline: 1.0088x; 1.0088x over previous
#include <cuda_runtime.h>
#include <cuda_fp16.h>
#include <math.h>
#include <stdint.h>

#define BATCH   8
#define SEQLEN  4096
#define DIM     512
#define MROWS   (BATCH * SEQLEN)   // 32768
#define CHUNK_S 64
#define NCHUNK_S (SEQLEN / CHUNK_S)  // 64

// ================= static scratch =================
// packed coefficients: lo = 1-a (fp16), hi = b (fp16)
__device__ __align__(16) __half2 g_ab[(size_t)MROWS * DIM];   // 64 MB
__device__ float g_P  [BATCH * NCHUNK_S * DIM];
__device__ float g_Q  [BATCH * NCHUNK_S * DIM];
__device__ float g_Hin[BATCH * NCHUNK_S * DIM];               // 8 MB

// fp16 operands. A3 = [hs | x] : 32768 x 1024
__device__ __align__(16) __half g_A3[(size_t)MROWS * 1024];
__device__ __align__(16) __half g_W1[1024 * 512];    // interleaved [Wg;B]
__device__ __align__(16) __half g_W3[512 * 1024];    // [C | D]

// ================= PTX helpers (sm_80+ family-safe) ========
__device__ __forceinline__ uint32_t smem_u32(const void* p) {
    uint32_t a;
    asm("{ .reg .u64 t; cvta.to.shared.u64 t, %1; cvt.u32.u64 %0, t; }"
        : "=r"(a) : "l"(p));
    return a;
}
__device__ __forceinline__ void cp16(uint32_t s, const void* g) {
    asm volatile("cp.async.cg.shared.global [%0], [%1], 16;"
                 :: "r"(s), "l"(__cvta_generic_to_global(g)) : "memory");
}
#define CP_COMMIT() asm volatile("cp.async.commit_group;" ::: "memory")
#define CP_WAIT(n)  asm volatile("cp.async.wait_group %0;" :: "n"(n) : "memory")

#define LDSM4(r0, r1, r2, r3, addr) \
    asm volatile("ldmatrix.sync.aligned.m8n8.x4.shared.b16 {%0,%1,%2,%3}, [%4];" \
                 : "=r"(r0), "=r"(r1), "=r"(r2), "=r"(r3) : "r"(addr))

#define MMAH(c, a, b0, b1) \
    asm volatile("mma.sync.aligned.m16n8k16.row.col.f32.f16.f16.f32 " \
                 "{%0,%1,%2,%3}, {%4,%5,%6,%7}, {%8,%9}, {%0,%1,%2,%3};" \
                 : "+f"((c)[0]), "+f"((c)[1]), "+f"((c)[2]), "+f"((c)[3]) \
                 : "r"((a)[0]), "r"((a)[1]), "r"((a)[2]), "r"((a)[3]), \
                   "r"(b0), "r"(b1))

// smem tile: 128 rows x 64 fp16 (128B data), row stride 144B.
// 144*r mod 128 over r=0..7 -> all eight 16B banks: ldmatrix conflict-free.
#define T_STRIDE 144
#define T_BYTES  (128 * T_STRIDE)          // 18432
#define BUF_BYTES (2 * T_BYTES)            // A + W = 36864
#define SMEM_REQ  (2 * BUF_BYTES)          // 73728 (double buffer; 3 CTAs/SM)

// =======================================================================
// merged conv kernel: W1, W3, and x->A3 in one launch
// =======================================================================
__global__ void conv_all_kernel(const float* __restrict__ Wg, const float* __restrict__ B,
                                const float* __restrict__ C,  const float* __restrict__ D,
                                const float* __restrict__ x)
{
    size_t idx = (size_t)blockIdx.x * blockDim.x + threadIdx.x;
    if (idx < 1024 * 512) {
        int r = (int)(idx >> 9), k = (int)(idx & 511), h = r >> 1;
        float v = (r & 1) ? B[h * 512 + k] : Wg[h * 512 + k];
        g_W1[idx] = __float2half_rn(v);
    } else if (idx < 2 * 1024 * 512) {
        int j = (int)(idx - 1024 * 512);
        int n = j >> 10, k = j & 1023;
        float v = (k < 512) ? C[n * 512 + k] : D[n * 512 + k - 512];
        g_W3[j] = __float2half_rn(v);
    } else {
        size_t j = idx - 2 * 1024 * 512;        // float4 index over x
        int cv = (int)(j & 127);
        int m  = (int)(j >> 7);
        float4 v = *(const float4*)&x[(size_t)m * 512 + cv * 4];
        size_t o = (size_t)m * 1024 + 512 + cv * 4;
        *(__half2*)&g_A3[o]     = __floats2half2_rn(v.x, v.y);
        *(__half2*)&g_A3[o + 2] = __floats2half2_rn(v.z, v.w);
    }
}

// =======================================================================
// HMMA mainloop: CTA 128x128, 4 warps, warp tile 64x64, K-chunk 64,
// 2-stage cp.async, single-fp16 operands
// =======================================================================
__device__ __forceinline__ void issue_chunk(
    uint32_t tb, int tid, int k0,
    const __half* __restrict__ A, int lda,
    const __half* __restrict__ W, int ldw)
{
    #pragma unroll
    for (int i = 0; i < 8; ++i) {
        int v = i * 128 + tid;              // 0..1023
        int r = v >> 3, ch = v & 7;         // row 0..127, 16B-chunk 0..7
        uint32_t so = (uint32_t)(r * T_STRIDE + ch * 16);
        int go = k0 + ch * 8;
        cp16(tb +           so, A + (size_t)r * lda + go);
        cp16(tb + T_BYTES + so, W + (size_t)r * ldw + go);
    }
    CP_COMMIT();
}

template<int NC>
__device__ __forceinline__ void hmma_mainloop(
    uint32_t sb,
    const __half* __restrict__ A, int lda,
    const __half* __restrict__ W, int ldw,
    float acc[4][8][4])
{
    const int tid  = threadIdx.x;
    const int wid  = tid >> 5, lane = tid & 31;
    const int wm   = (wid >> 1) * 64;
    const int wn   = (wid & 1) * 64;
    const uint32_t aSel = (uint32_t)((lane & 15) * T_STRIDE + (lane >> 4) * 16);
    const uint32_t bSel = (uint32_t)((((lane >> 4) << 3) + (lane & 7)) * T_STRIDE
                                     + ((lane >> 3) & 1) * 16);

    issue_chunk(sb,             tid, 0,  A, lda, W, ldw);
    issue_chunk(sb + BUF_BYTES, tid, 64, A, lda, W, ldw);

    #pragma unroll 1
    for (int c = 0; c < NC; ++c) {
        if (c + 1 == NC) { CP_WAIT(0); } else { CP_WAIT(1); }
        __syncthreads();

        const uint32_t tb = sb + (uint32_t)(c & 1) * BUF_BYTES;
        const uint32_t At = tb + (uint32_t)wm * T_STRIDE + aSel;
        const uint32_t Wt = tb + T_BYTES + (uint32_t)wn * T_STRIDE + bSel;

        #pragma unroll
        for (int kk = 0; kk < 4; ++kk) {
            const uint32_t ko = kk * 32;    // 16 fp16 = 32B per k16 step
            uint32_t ah[4][4];
            #pragma unroll
            for (int mb = 0; mb < 4; ++mb)
                LDSM4(ah[mb][0], ah[mb][1], ah[mb][2], ah[mb][3],
                      At + mb * (16 * T_STRIDE) + ko);
            #pragma unroll
            for (int nb = 0; nb < 4; ++nb) {
                uint32_t wh[4];
                LDSM4(wh[0], wh[1], wh[2], wh[3], Wt + nb * (16 * T_STRIDE) + ko);
                #pragma unroll
                for (int mb = 0; mb < 4; ++mb) {
                    MMAH(acc[mb][2 * nb],     ah[mb], wh[0], wh[1]);
                    MMAH(acc[mb][2 * nb + 1], ah[mb], wh[2], wh[3]);
                }
            }
        }
        __syncthreads();
        if (c + 2 < NC)
            issue_chunk(sb + (uint32_t)(c & 1) * BUF_BYTES, tid, (c + 2) * 64,
                        A, lda, W, ldw);
    }
}

// =======================================================================
// Stage 1: raw = x @ W1^T (M=32768, N=1024, K=512) -> (1-a, b) fp16 + P,Q
// grid (8, 256), 128 threads
// =======================================================================
__global__ __launch_bounds__(128, 3)
void hmma_stage1_kernel(const float* __restrict__ Avec,
                        const float* __restrict__ bias_h)
{
    extern __shared__ __align__(16) char smem[];
    const uint32_t sb = smem_u32(smem);

    float acc[4][8][4];
    #pragma unroll
    for (int i = 0; i < 4; ++i)
        #pragma unroll
        for (int j = 0; j < 8; ++j)
            #pragma unroll
            for (int q = 0; q < 4; ++q) acc[i][j][q] = 0.f;

    const int row0 = blockIdx.y * 128;
    const int col0 = blockIdx.x * 128;

    hmma_mainloop<8>(sb,
                     g_A3 + 512 + (size_t)row0 * 1024, 1024,
                     g_W1 + (size_t)col0 * 512, 512,
                     acc);

    // -------- epilogue: gate math, quantize (1-a, b) to fp16, restage ------
    const int tid = threadIdx.x, wid = tid >> 5, lane = tid & 31;
    const int wm = (wid >> 1) * 64, wn = (wid & 1) * 64;
    const int g = lane >> 2, tig = lane & 3;
    const int hbase = col0 >> 1;

    float* sA = (float*)smem;              // [128][65]  quantized (1-a)
    float* sB = sA + 128 * 65;             // [128][65]  quantized b

    #pragma unroll
    for (int mb = 0; mb < 4; ++mb) {
        #pragma unroll
        for (int j = 0; j < 8; ++j) {
            int h_loc = (wn + (j >> 1) * 16 + (j & 1) * 8 + 2 * tig) >> 1;
            int hg = hbase + h_loc;
            float Ah = Avec[hg], Bh = bias_h[hg];
            int m0 = wm + mb * 16 + g;

            float g0 = 1.0f / (1.0f + __expf(-acc[mb][j][0]));
            g0 = fminf(fmaxf(g0, 0.05f), 0.95f);
            sA[m0 * 65 + h_loc] = __half2float(__float2half_rn(g0 * (1.0f - Ah)));
            sB[m0 * 65 + h_loc] = __half2float(__float2half_rn(g0 * (acc[mb][j][1] + Bh)));

            float g1 = 1.0f / (1.0f + __expf(-acc[mb][j][2]));
            g1 = fminf(fmaxf(g1, 0.05f), 0.95f);
            sA[(m0 + 8) * 65 + h_loc] = __half2float(__float2half_rn(g1 * (1.0f - Ah)));
            sB[(m0 + 8) * 65 + h_loc] = __half2float(__float2half_rn(g1 * (acc[mb][j][3] + Bh)));
        }
    }
    __syncthreads();

    // coalesced packed write (values already half-representable -> exact)
    const int hh = tid & 63, rg = tid >> 6;
    #pragma unroll
    for (int r = 0; r < 64; ++r) {
        int row = rg * 64 + r;
        size_t gb = (size_t)(row0 + row) * DIM + hbase + hh;
        g_ab[gb] = __floats2half2_rn(sA[row * 65 + hh], sB[row * 65 + hh]);
    }

    // sub-chunk summaries (64 rows): P = prod(a), Q = local final (h_in=0),
    // computed from the QUANTIZED coefficients for exact carry consistency.
    {
        const int sc = tid >> 6;           // 0..1
        const int hl = tid & 63;
        float p = 1.0f, q = 0.0f;
        #pragma unroll 4
        for (int r = sc * 64; r < sc * 64 + 64; ++r) {
            float a  = 1.0f - sA[r * 65 + hl];
            float bb = sB[r * 65 + hl];
            q = fmaf(a, q, bb);
            p *= a;
        }
        size_t o = ((size_t)blockIdx.y * 2 + sc) * DIM + hbase + hl;
        g_P[o] = p;
        g_Q[o] = q;
    }
}

// =======================================================================
// carry: Hillis-Steele log-depth scan of affine maps over the 64 chunks.
// grid 512 (b = blk>>6, h-group = blk&63 covering 8 h), block 512
// (c = tid>>3, hl = tid&7). Exclusive prefix -> g_Hin.
// =======================================================================
__global__ __launch_bounds__(512) void scan_carry_kernel()
{
    __shared__ float sP[64][8];
    __shared__ float sQ[64][8];
    const int b  = blockIdx.x >> 6;
    const int hg = blockIdx.x & 63;
    const int tid = threadIdx.x;
    const int c  = tid >> 3, hl = tid & 7;
    const int h  = hg * 8 + hl;
    const size_t o = ((size_t)b * NCHUNK_S + c) * DIM + h;

    float p = g_P[o], q = g_Q[o];
    sP[c][hl] = p; sQ[c][hl] = q;
    __syncthreads();

    #pragma unroll
    for (int d = 1; d < 64; d <<= 1) {
        float pp = 1.0f, pq = 0.0f;
        if (c >= d) { pp = sP[c - d][hl]; pq = sQ[c - d][hl]; }
        __syncthreads();
        if (c >= d) { q = fmaf(p, pq, q); p *= pp; }
        sP[c][hl] = p; sQ[c][hl] = q;
        __syncthreads();
    }

    // exclusive prefix: Hin[c] = (c==0) ? 0 : inclusive[c-1].Q
    g_Hin[o] = (c == 0) ? 0.0f : sQ[c - 1][hl];
}

// =======================================================================
// final scan (R13 measured-good config): 256 threads x 2 adjacent h each;
// 8B coefficient loads, 4B fp16 stores. grid 512.
// =======================================================================
__global__ __launch_bounds__(256) void scan_final_kernel()
{
    const int bc = blockIdx.x;            // b*64 + cs
    const int b  = bc >> 6;
    const int cs = bc & 63;
    const int h0 = threadIdx.x * 2;       // even h

    float2 hin = *(const float2*)&g_Hin[(size_t)bc * DIM + h0];
    float hc0 = hin.x, hc1 = hin.y;

    const size_t base = ((size_t)b * SEQLEN + (size_t)cs * CHUNK_S) * DIM + h0;
    #pragma unroll 8
    for (int t = 0; t < CHUNK_S; ++t) {
        float2 r = *reinterpret_cast<const float2*>(&g_ab[base + (size_t)t * DIM]);
        __half2 ab0 = *reinterpret_cast<__half2*>(&r.x);
        __half2 ab1 = *reinterpret_cast<__half2*>(&r.y);
        float a0 = 1.0f - __half2float(__low2half(ab0));
        float b0 = __half2float(__high2half(ab0));
        float a1 = 1.0f - __half2float(__low2half(ab1));
        float b1 = __half2float(__high2half(ab1));
        hc0 = fmaf(a0, hc0, b0);
        hc1 = fmaf(a1, hc1, b1);
        const size_t m = (size_t)(b * SEQLEN + cs * CHUNK_S + t);
        *(__half2*)&g_A3[m * 1024 + h0] = __floats2half2_rn(hc0, hc1);
    }
}

// =======================================================================
// Stage 3: y = (hs@C^T + x@D^T + bias_y)*scale, K=1024, single-fp16 W
// grid (4, 256), 128 threads
// =======================================================================
__global__ __launch_bounds__(128, 3)
void hmma_stage3_kernel(const float* __restrict__ bias_y, float* __restrict__ out)
{
    extern __shared__ __align__(16) char smem[];
    const uint32_t sb = smem_u32(smem);

    float acc[4][8][4];
    #pragma unroll
    for (int i = 0; i < 4; ++i)
        #pragma unroll
        for (int j = 0; j < 8; ++j)
            #pragma unroll
            for (int q = 0; q < 4; ++q) acc[i][j][q] = 0.f;

    const int row0 = blockIdx.y * 128;
    const int col0 = blockIdx.x * 128;

    hmma_mainloop<16>(sb,
                      g_A3 + (size_t)row0 * 1024, 1024,
                      g_W3 + (size_t)col0 * 1024, 1024,
                      acc);

    const int tid = threadIdx.x, wid = tid >> 5, lane = tid & 31;
    const int wm = (wid >> 1) * 64, wn = (wid & 1) * 64;
    const int g = lane >> 2, tig = lane & 3;
    const float scale = 0.04419417382415922f;   // 1/sqrt(512)

    float* sY = (float*)smem;                   // [128][132]

    #pragma unroll
    for (int mb = 0; mb < 4; ++mb) {
        #pragma unroll
        for (int j = 0; j < 8; ++j) {
            int n0 = wn + (j >> 1) * 16 + (j & 1) * 8 + 2 * tig;
            float by0 = bias_y[col0 + n0], by1 = bias_y[col0 + n0 + 1];
            int m0 = wm + mb * 16 + g;
            sY[m0 * 132 + n0]           = (acc[mb][j][0] + by0) * scale;
            sY[m0 * 132 + n0 + 1]       = (acc[mb][j][1] + by1) * scale;
            sY[(m0 + 8) * 132 + n0]     = (acc[mb][j][2] + by0) * scale;
            sY[(m0 + 8) * 132 + n0 + 1] = (acc[mb][j][3] + by1) * scale;
        }
    }
    __syncthreads();

    // vectorized store: 4096 float4 over 128 threads = 32 iterations
    #pragma unroll 8
    for (int i = 0; i < 32; ++i) {
        int v   = i * 128 + tid;
        int row = v >> 5;
        int c4  = v & 31;
        float4 val = *(const float4*)&sY[row * 132 + c4 * 4];
        *(float4*)&out[(size_t)(row0 + row) * DIM + col0 + c4 * 4] = val;
    }
}

// =======================================================================
extern "C" void kernel_launch(void* const* d_in, const int* in_sizes, int n_in,
                              void* d_out, int out_size)
{
    const float* x      = (const float*)d_in[0];
    const float* Avec   = (const float*)d_in[1];
    const float* B      = (const float*)d_in[2];
    const float* C      = (const float*)d_in[3];
    const float* Dm     = (const float*)d_in[4];
    const float* Wg     = (const float*)d_in[5];
    const float* bias_h = (const float*)d_in[6];
    const float* bias_y = (const float*)d_in[7];
    float* out = (float*)d_out;

    cudaFuncSetAttribute(hmma_stage1_kernel,
                         cudaFuncAttributeMaxDynamicSharedMemorySize, SMEM_REQ);
    cudaFuncSetAttribute(hmma_stage3_kernel,
                         cudaFuncAttributeMaxDynamicSharedMemorySize, SMEM_REQ);

    // merged conversions: W1 + W3 + x->A3
    const int conv_items = 2 * 1024 * 512 + MROWS * (DIM / 4);
    conv_all_kernel<<<conv_items / 256, 256>>>(Wg, B, C, Dm, x);

    hmma_stage1_kernel<<<dim3(8, MROWS / 128), 128, SMEM_REQ>>>(Avec, bias_h);

    scan_carry_kernel<<<BATCH * 64, 512>>>();
    scan_final_kernel<<<BATCH * NCHUNK_S, 256>>>();

    hmma_stage3_kernel<<<dim3(4, MROWS / 128), 128, SMEM_REQ>>>(bias_y, out);
}

// round 17
// speedup vs baseline: 1.0408x; 1.0317x over previous
#include <cuda_runtime.h>
#include <cuda_fp16.h>
#include <math.h>
#include <stdint.h>

#define BATCH   8
#define SEQLEN  4096
#define DIM     512
#define MROWS   (BATCH * SEQLEN)   // 32768
#define CHUNK_S 32
#define NCHUNK_S (SEQLEN / CHUNK_S)  // 128

// ================= static scratch =================
// packed coefficients: lo = 1-a (fp16), hi = b (fp16)
__device__ __align__(16) __half2 g_ab[(size_t)MROWS * DIM];   // 64 MB
__device__ float g_P  [BATCH * NCHUNK_S * DIM];               // 2 MB
__device__ float g_Q  [BATCH * NCHUNK_S * DIM];
__device__ float g_Hin[BATCH * NCHUNK_S * DIM];

// fp16 operands. A3 = [hs | x] : 32768 x 1024
__device__ __align__(16) __half g_A3[(size_t)MROWS * 1024];
__device__ __align__(16) __half g_W1[1024 * 512];    // interleaved [Wg;B]
__device__ __align__(16) __half g_W3[512 * 1024];    // [C | D]

// ================= PTX helpers (sm_80+ family-safe) ========
__device__ __forceinline__ uint32_t smem_u32(const void* p) {
    uint32_t a;
    asm("{ .reg .u64 t; cvta.to.shared.u64 t, %1; cvt.u32.u64 %0, t; }"
        : "=r"(a) : "l"(p));
    return a;
}
__device__ __forceinline__ void cp16(uint32_t s, const void* g) {
    asm volatile("cp.async.cg.shared.global [%0], [%1], 16;"
                 :: "r"(s), "l"(__cvta_generic_to_global(g)) : "memory");
}
#define CP_COMMIT() asm volatile("cp.async.commit_group;" ::: "memory")
#define CP_WAIT(n)  asm volatile("cp.async.wait_group %0;" :: "n"(n) : "memory")

#define LDSM4(r0, r1, r2, r3, addr) \
    asm volatile("ldmatrix.sync.aligned.m8n8.x4.shared.b16 {%0,%1,%2,%3}, [%4];" \
                 : "=r"(r0), "=r"(r1), "=r"(r2), "=r"(r3) : "r"(addr))

#define MMAH(c, a, b0, b1) \
    asm volatile("mma.sync.aligned.m16n8k16.row.col.f32.f16.f16.f32 " \
                 "{%0,%1,%2,%3}, {%4,%5,%6,%7}, {%8,%9}, {%0,%1,%2,%3};" \
                 : "+f"((c)[0]), "+f"((c)[1]), "+f"((c)[2]), "+f"((c)[3]) \
                 : "r"((a)[0]), "r"((a)[1]), "r"((a)[2]), "r"((a)[3]), \
                   "r"(b0), "r"(b1))

// smem tile: 128 rows x 64 fp16 (128B data), row stride 144B.
// 144*r mod 128 over r=0..7 -> all eight 16B banks: ldmatrix conflict-free.
#define T_STRIDE 144
#define T_BYTES  (128 * T_STRIDE)          // 18432
#define BUF_BYTES (2 * T_BYTES)            // A + W = 36864
#define SMEM_REQ  (2 * BUF_BYTES)          // 73728 (double buffer; 3 CTAs/SM)

// =======================================================================
// merged conv kernel: W1, W3, and x->A3 in one launch
// =======================================================================
__global__ void conv_all_kernel(const float* __restrict__ Wg, const float* __restrict__ B,
                                const float* __restrict__ C,  const float* __restrict__ D,
                                const float* __restrict__ x)
{
    size_t idx = (size_t)blockIdx.x * blockDim.x + threadIdx.x;
    if (idx < 1024 * 512) {
        int r = (int)(idx >> 9), k = (int)(idx & 511), h = r >> 1;
        float v = (r & 1) ? B[h * 512 + k] : Wg[h * 512 + k];
        g_W1[idx] = __float2half_rn(v);
    } else if (idx < 2 * 1024 * 512) {
        int j = (int)(idx - 1024 * 512);
        int n = j >> 10, k = j & 1023;
        float v = (k < 512) ? C[n * 512 + k] : D[n * 512 + k - 512];
        g_W3[j] = __float2half_rn(v);
    } else {
        size_t j = idx - 2 * 1024 * 512;        // float4 index over x
        int cv = (int)(j & 127);
        int m  = (int)(j >> 7);
        float4 v = *(const float4*)&x[(size_t)m * 512 + cv * 4];
        size_t o = (size_t)m * 1024 + 512 + cv * 4;
        *(__half2*)&g_A3[o]     = __floats2half2_rn(v.x, v.y);
        *(__half2*)&g_A3[o + 2] = __floats2half2_rn(v.z, v.w);
    }
}

// =======================================================================
// HMMA mainloop: CTA 128x128, 4 warps, warp tile 64x64, K-chunk 64,
// 2-stage cp.async, single-fp16 operands
// =======================================================================
__device__ __forceinline__ void issue_chunk(
    uint32_t tb, int tid, int k0,
    const __half* __restrict__ A, int lda,
    const __half* __restrict__ W, int ldw)
{
    #pragma unroll
    for (int i = 0; i < 8; ++i) {
        int v = i * 128 + tid;              // 0..1023
        int r = v >> 3, ch = v & 7;         // row 0..127, 16B-chunk 0..7
        uint32_t so = (uint32_t)(r * T_STRIDE + ch * 16);
        int go = k0 + ch * 8;
        cp16(tb +           so, A + (size_t)r * lda + go);
        cp16(tb + T_BYTES + so, W + (size_t)r * ldw + go);
    }
    CP_COMMIT();
}

template<int NC>
__device__ __forceinline__ void hmma_mainloop(
    uint32_t sb,
    const __half* __restrict__ A, int lda,
    const __half* __restrict__ W, int ldw,
    float acc[4][8][4])
{
    const int tid  = threadIdx.x;
    const int wid  = tid >> 5, lane = tid & 31;
    const int wm   = (wid >> 1) * 64;
    const int wn   = (wid & 1) * 64;
    const uint32_t aSel = (uint32_t)((lane & 15) * T_STRIDE + (lane >> 4) * 16);
    const uint32_t bSel = (uint32_t)((((lane >> 4) << 3) + (lane & 7)) * T_STRIDE
                                     + ((lane >> 3) & 1) * 16);

    issue_chunk(sb,             tid, 0,  A, lda, W, ldw);
    issue_chunk(sb + BUF_BYTES, tid, 64, A, lda, W, ldw);

    #pragma unroll 1
    for (int c = 0; c < NC; ++c) {
        if (c + 1 == NC) { CP_WAIT(0); } else { CP_WAIT(1); }
        __syncthreads();

        const uint32_t tb = sb + (uint32_t)(c & 1) * BUF_BYTES;
        const uint32_t At = tb + (uint32_t)wm * T_STRIDE + aSel;
        const uint32_t Wt = tb + T_BYTES + (uint32_t)wn * T_STRIDE + bSel;

        #pragma unroll
        for (int kk = 0; kk < 4; ++kk) {
            const uint32_t ko = kk * 32;    // 16 fp16 = 32B per k16 step
            uint32_t ah[4][4];
            #pragma unroll
            for (int mb = 0; mb < 4; ++mb)
                LDSM4(ah[mb][0], ah[mb][1], ah[mb][2], ah[mb][3],
                      At + mb * (16 * T_STRIDE) + ko);
            #pragma unroll
            for (int nb = 0; nb < 4; ++nb) {
                uint32_t wh[4];
                LDSM4(wh[0], wh[1], wh[2], wh[3], Wt + nb * (16 * T_STRIDE) + ko);
                #pragma unroll
                for (int mb = 0; mb < 4; ++mb) {
                    MMAH(acc[mb][2 * nb],     ah[mb], wh[0], wh[1]);
                    MMAH(acc[mb][2 * nb + 1], ah[mb], wh[2], wh[3]);
                }
            }
        }
        __syncthreads();
        if (c + 2 < NC)
            issue_chunk(sb + (uint32_t)(c & 1) * BUF_BYTES, tid, (c + 2) * 64,
                        A, lda, W, ldw);
    }
}

// =======================================================================
// Stage 1: raw = x @ W1^T (M=32768, N=1024, K=512) -> (1-a, b) fp16 + P,Q
// grid (8, 256), 128 threads. P,Q at 32-row sub-chunk granularity (4/tile).
// =======================================================================
__global__ __launch_bounds__(128, 3)
void hmma_stage1_kernel(const float* __restrict__ Avec,
                        const float* __restrict__ bias_h)
{
    extern __shared__ __align__(16) char smem[];
    const uint32_t sb = smem_u32(smem);

    float acc[4][8][4];
    #pragma unroll
    for (int i = 0; i < 4; ++i)
        #pragma unroll
        for (int j = 0; j < 8; ++j)
            #pragma unroll
            for (int q = 0; q < 4; ++q) acc[i][j][q] = 0.f;

    const int row0 = blockIdx.y * 128;
    const int col0 = blockIdx.x * 128;

    hmma_mainloop<8>(sb,
                     g_A3 + 512 + (size_t)row0 * 1024, 1024,
                     g_W1 + (size_t)col0 * 512, 512,
                     acc);

    // -------- epilogue: gate math, quantize (1-a, b) to fp16, restage ------
    const int tid = threadIdx.x, wid = tid >> 5, lane = tid & 31;
    const int wm = (wid >> 1) * 64, wn = (wid & 1) * 64;
    const int g = lane >> 2, tig = lane & 3;
    const int hbase = col0 >> 1;

    float* sA = (float*)smem;              // [128][65]  quantized (1-a)
    float* sB = sA + 128 * 65;             // [128][65]  quantized b

    #pragma unroll
    for (int mb = 0; mb < 4; ++mb) {
        #pragma unroll
        for (int j = 0; j < 8; ++j) {
            int h_loc = (wn + (j >> 1) * 16 + (j & 1) * 8 + 2 * tig) >> 1;
            int hg = hbase + h_loc;
            float Ah = Avec[hg], Bh = bias_h[hg];
            int m0 = wm + mb * 16 + g;

            float g0 = 1.0f / (1.0f + __expf(-acc[mb][j][0]));
            g0 = fminf(fmaxf(g0, 0.05f), 0.95f);
            sA[m0 * 65 + h_loc] = __half2float(__float2half_rn(g0 * (1.0f - Ah)));
            sB[m0 * 65 + h_loc] = __half2float(__float2half_rn(g0 * (acc[mb][j][1] + Bh)));

            float g1 = 1.0f / (1.0f + __expf(-acc[mb][j][2]));
            g1 = fminf(fmaxf(g1, 0.05f), 0.95f);
            sA[(m0 + 8) * 65 + h_loc] = __half2float(__float2half_rn(g1 * (1.0f - Ah)));
            sB[(m0 + 8) * 65 + h_loc] = __half2float(__float2half_rn(g1 * (acc[mb][j][3] + Bh)));
        }
    }
    __syncthreads();

    // coalesced packed write (values already half-representable -> exact)
    const int hh = tid & 63, rg = tid >> 6;
    #pragma unroll
    for (int r = 0; r < 64; ++r) {
        int row = rg * 64 + r;
        size_t gb = (size_t)(row0 + row) * DIM + hbase + hh;
        g_ab[gb] = __floats2half2_rn(sA[row * 65 + hh], sB[row * 65 + hh]);
    }

    // sub-chunk summaries (32 rows x 4): each thread handles 2 sub-chunks.
    // Computed from the QUANTIZED coefficients for exact carry consistency.
    {
        const int hl = tid & 63;
        const int s0 = tid >> 6;           // 0..1
        #pragma unroll
        for (int ss = 0; ss < 2; ++ss) {
            const int sc = s0 * 2 + ss;    // 0..3
            float p = 1.0f, q = 0.0f;
            #pragma unroll 4
            for (int r = sc * 32; r < sc * 32 + 32; ++r) {
                float a  = 1.0f - sA[r * 65 + hl];
                float bb = sB[r * 65 + hl];
                q = fmaf(a, q, bb);
                p *= a;
            }
            size_t o = ((size_t)blockIdx.y * 4 + sc) * DIM + hbase + hl;
            g_P[o] = p;
            g_Q[o] = q;
        }
    }
}

// =======================================================================
// carry: Hillis-Steele log-depth scan of affine maps over 128 chunks.
// grid 1024 (b = blk>>7, h-group = blk&127 covering 4 h), block 512
// (c = tid>>2, hl = tid&3). Exclusive prefix -> g_Hin.
// =======================================================================
__global__ __launch_bounds__(512) void scan_carry_kernel()
{
    __shared__ float sP[128][4];
    __shared__ float sQ[128][4];
    const int b  = blockIdx.x >> 7;
    const int hg = blockIdx.x & 127;
    const int tid = threadIdx.x;
    const int c  = tid >> 2, hl = tid & 3;
    const int h  = hg * 4 + hl;
    const size_t o = ((size_t)b * NCHUNK_S + c) * DIM + h;

    float p = g_P[o], q = g_Q[o];
    sP[c][hl] = p; sQ[c][hl] = q;
    __syncthreads();

    #pragma unroll
    for (int d = 1; d < 128; d <<= 1) {
        float pp = 1.0f, pq = 0.0f;
        if (c >= d) { pp = sP[c - d][hl]; pq = sQ[c - d][hl]; }
        __syncthreads();
        if (c >= d) { q = fmaf(p, pq, q); p *= pp; }
        sP[c][hl] = p; sQ[c][hl] = q;
        __syncthreads();
    }

    // exclusive prefix: Hin[c] = (c==0) ? 0 : inclusive[c-1].Q
    g_Hin[o] = (c == 0) ? 0.0f : sQ[c - 1][hl];
}

// =======================================================================
// final scan: 256 threads x 2 adjacent h; 32-step t-loop. grid 1024.
// =======================================================================
__global__ __launch_bounds__(256) void scan_final_kernel()
{
    const int bc = blockIdx.x;            // b*128 + cs
    const int b  = bc >> 7;
    const int cs = bc & 127;
    const int h0 = threadIdx.x * 2;       // even h

    float2 hin = *(const float2*)&g_Hin[(size_t)bc * DIM + h0];
    float hc0 = hin.x, hc1 = hin.y;

    const size_t base = ((size_t)b * SEQLEN + (size_t)cs * CHUNK_S) * DIM + h0;
    #pragma unroll 8
    for (int t = 0; t < CHUNK_S; ++t) {
        float2 r = *reinterpret_cast<const float2*>(&g_ab[base + (size_t)t * DIM]);
        __half2 ab0 = *reinterpret_cast<__half2*>(&r.x);
        __half2 ab1 = *reinterpret_cast<__half2*>(&r.y);
        float a0 = 1.0f - __half2float(__low2half(ab0));
        float b0 = __half2float(__high2half(ab0));
        float a1 = 1.0f - __half2float(__low2half(ab1));
        float b1 = __half2float(__high2half(ab1));
        hc0 = fmaf(a0, hc0, b0);
        hc1 = fmaf(a1, hc1, b1);
        const size_t m = (size_t)(b * SEQLEN + cs * CHUNK_S + t);
        *(__half2*)&g_A3[m * 1024 + h0] = __floats2half2_rn(hc0, hc1);
    }
}

// =======================================================================
// Stage 3: y = (hs@C^T + x@D^T + bias_y)*scale, K=1024, single-fp16 W
// grid (4, 256), 128 threads
// =======================================================================
__global__ __launch_bounds__(128, 3)
void hmma_stage3_kernel(const float* __restrict__ bias_y, float* __restrict__ out)
{
    extern __shared__ __align__(16) char smem[];
    const uint32_t sb = smem_u32(smem);

    float acc[4][8][4];
    #pragma unroll
    for (int i = 0; i < 4; ++i)
        #pragma unroll
        for (int j = 0; j < 8; ++j)
            #pragma unroll
            for (int q = 0; q < 4; ++q) acc[i][j][q] = 0.f;

    const int row0 = blockIdx.y * 128;
    const int col0 = blockIdx.x * 128;

    hmma_mainloop<16>(sb,
                      g_A3 + (size_t)row0 * 1024, 1024,
                      g_W3 + (size_t)col0 * 1024, 1024,
                      acc);

    const int tid = threadIdx.x, wid = tid >> 5, lane = tid & 31;
    const int wm = (wid >> 1) * 64, wn = (wid & 1) * 64;
    const int g = lane >> 2, tig = lane & 3;
    const float scale = 0.04419417382415922f;   // 1/sqrt(512)

    float* sY = (float*)smem;                   // [128][132]

    #pragma unroll
    for (int mb = 0; mb < 4; ++mb) {
        #pragma unroll
        for (int j = 0; j < 8; ++j) {
            int n0 = wn + (j >> 1) * 16 + (j & 1) * 8 + 2 * tig;
            float by0 = bias_y[col0 + n0], by1 = bias_y[col0 + n0 + 1];
            int m0 = wm + mb * 16 + g;
            sY[m0 * 132 + n0]           = (acc[mb][j][0] + by0) * scale;
            sY[m0 * 132 + n0 + 1]       = (acc[mb][j][1] + by1) * scale;
            sY[(m0 + 8) * 132 + n0]     = (acc[mb][j][2] + by0) * scale;
            sY[(m0 + 8) * 132 + n0 + 1] = (acc[mb][j][3] + by1) * scale;
        }
    }
    __syncthreads();

    // vectorized store: 4096 float4 over 128 threads = 32 iterations
    #pragma unroll 8
    for (int i = 0; i < 32; ++i) {
        int v   = i * 128 + tid;
        int row = v >> 5;
        int c4  = v & 31;
        float4 val = *(const float4*)&sY[row * 132 + c4 * 4];
        *(float4*)&out[(size_t)(row0 + row) * DIM + col0 + c4 * 4] = val;
    }
}

// =======================================================================
extern "C" void kernel_launch(void* const* d_in, const int* in_sizes, int n_in,
                              void* d_out, int out_size)
{
    const float* x      = (const float*)d_in[0];
    const float* Avec   = (const float*)d_in[1];
    const float* B      = (const float*)d_in[2];
    const float* C      = (const float*)d_in[3];
    const float* Dm     = (const float*)d_in[4];
    const float* Wg     = (const float*)d_in[5];
    const float* bias_h = (const float*)d_in[6];
    const float* bias_y = (const float*)d_in[7];
    float* out = (float*)d_out;

    cudaFuncSetAttribute(hmma_stage1_kernel,
                         cudaFuncAttributeMaxDynamicSharedMemorySize, SMEM_REQ);
    cudaFuncSetAttribute(hmma_stage3_kernel,
                         cudaFuncAttributeMaxDynamicSharedMemorySize, SMEM_REQ);

    // merged conversions: W1 + W3 + x->A3
    const int conv_items = 2 * 1024 * 512 + MROWS * (DIM / 4);
    conv_all_kernel<<<conv_items / 256, 256>>>(Wg, B, C, Dm, x);

    hmma_stage1_kernel<<<dim3(8, MROWS / 128), 128, SMEM_REQ>>>(Avec, bias_h);

    scan_carry_kernel<<<BATCH * 128, 512>>>();
    scan_final_kernel<<<BATCH * NCHUNK_S, 256>>>();

    hmma_stage3_kernel<<<dim3(4, MROWS / 128), 128, SMEM_REQ>>>(bias_y, out);
}